// round 16
// baseline (speedup 1.0000x reference)
#include <cuda_runtime.h>
#include <cuda_bf16.h>
#include <cstdint>

// ---------------- problem constants ----------------
#define BATCH   2
#define SEQ     2048
#define TOK     (BATCH * SEQ)        // 4096
#define DM      768                  // d_model
#define DI      1536                 // d_inner
#define DI2     (2 * DI)             // 3072
#define NSTATE  16
#define NX      33                   // 1 + 2*NSTATE
#define DCONV   4
#define NC      16                   // scan chunks
#define LCH     (SEQ / NC)           // 128 timesteps per chunk

typedef __nv_bfloat16 bf16;

// ---------------- scratch (static device globals) --------
__device__ __align__(16) bf16  g_xn_h [TOK * DM];
__device__ __align__(16) bf16  g_win_h[2ll * DI2 * DM];
__device__ __align__(16) bf16  g_wout_h[2ll * DM * DI];
__device__ __align__(16) bf16  g_gh [2ll * TOK * DI];
__device__ __align__(16) float  g_xz   [2ll * TOK * DI2];
__device__ __align__(16) float  g_xc   [2ll * TOK * DI];
__device__ __align__(16) float2 g_bc [2ll * TOK * NSTATE];
__device__ __align__(16) float  g_dt   [2ll * TOK * DI];
__device__ float  g_yp   [2ll * TOK * DM];
// parallel-scan intermediates: [dirb(4)][NC][DI*NSTATE]
__device__ __align__(16) float g_P  [4ll * NC * DI * NSTATE];
__device__ __align__(16) float g_Hl [4ll * NC * DI * NSTATE];
__device__ __align__(16) float g_Hin[4ll * NC * DI * NSTATE];

// ================= helpers =================
__device__ __forceinline__ uint32_t s2u(const void* p) {
    uint32_t a;
    asm("{ .reg .u64 t; cvta.to.shared.u64 t, %1; cvt.u32.u64 %0, t; }"
        : "=r"(a) : "l"(p));
    return a;
}
__device__ __forceinline__ uint32_t swz(uint32_t off) {
    return off ^ ((off >> 3) & 0x70);
}
__device__ __forceinline__ void cpasync16(uint32_t dst, const void* src) {
    asm volatile("cp.async.cg.shared.global [%0], [%1], 16;" :: "r"(dst), "l"(src) : "memory");
}
#define CP_COMMIT() asm volatile("cp.async.commit_group;" ::: "memory")
#define CP_WAIT0()  asm volatile("cp.async.wait_group 0;" ::: "memory")
#define CP_WAIT1()  asm volatile("cp.async.wait_group 1;" ::: "memory")

__device__ __forceinline__ void ldsm4(uint32_t* r, uint32_t addr) {
    asm volatile("ldmatrix.sync.aligned.m8n8.x4.shared.b16 {%0,%1,%2,%3}, [%4];"
                 : "=r"(r[0]), "=r"(r[1]), "=r"(r[2]), "=r"(r[3]) : "r"(addr));
}
__device__ __forceinline__ void mma16816(float* c, const uint32_t* a,
                                         uint32_t b0, uint32_t b1) {
    asm volatile(
        "mma.sync.aligned.m16n8k16.row.col.f32.bf16.bf16.f32 "
        "{%0,%1,%2,%3}, {%4,%5,%6,%7}, {%8,%9}, {%0,%1,%2,%3};"
        : "+f"(c[0]), "+f"(c[1]), "+f"(c[2]), "+f"(c[3])
        : "r"(a[0]), "r"(a[1]), "r"(a[2]), "r"(a[3]), "r"(b0), "r"(b1));
}

// ================= mma.sync GEMM (unchanged from R15) ======================
#define BK 64
#define TILE_B 16384
#define STAGE_B (4 * TILE_B)
#define NSTG 3

__global__ __launch_bounds__(512, 1)
void mma_gemm(const bf16* __restrict__ Ah, const bf16* __restrict__ Al,
              const bf16* __restrict__ Bh, const bf16* __restrict__ Bl,
              float* __restrict__ C, int M, int N, int K, int aPerDir, int flipA,
              int passes)
{
    extern __shared__ __align__(1024) char smem[];
    const int dir   = blockIdx.z;
    const int mBase = blockIdx.y * 128;
    const int nBase = blockIdx.x * 128;
    const uint32_t sb = s2u(smem);
    const int tid = threadIdx.x, wid = tid >> 5, lane = tid & 31;
    const int wm = wid & 3, wn = wid >> 2;

    const bf16* Ahp = Ah + (aPerDir ? (size_t)dir * M * K : 0);
    const bf16* Alp = Al + (aPerDir ? (size_t)dir * M * K : 0);
    const bf16* Bhp = Bh + (size_t)dir * (size_t)N * K;
    const bf16* Blp = Bl + (size_t)dir * (size_t)N * K;

    const int CK = K / BK;

    float acc[2][4][4];
    #pragma unroll
    for (int i = 0; i < 2; i++)
        #pragma unroll
        for (int j = 0; j < 4; j++)
            #pragma unroll
            for (int q = 0; q < 4; q++) acc[i][j][q] = 0.f;

    auto issue = [&](int c, int st) {
        const int k0 = c * BK;
        #pragma unroll
        for (int i = 0; i < 8; ++i) {
            int q     = tid + 512 * i;
            int which = q >> 10;
            if (which == 1 && passes < 2) continue;
            if (which == 3 && passes < 3) continue;
            int t     = q & 1023;
            int row   = t >> 3;
            int kb    = t & 7;
            const bf16* src;
            if (which < 2) {
                int grow = mBase + row;
                if (flipA && dir) grow ^= (SEQ - 1);
                src = (which ? Alp : Ahp) + (size_t)grow * K + k0 + kb * 8;
            } else {
                src = ((which == 3) ? Blp : Bhp) + (size_t)(nBase + row) * K + k0 + kb * 8;
            }
            uint32_t dst = sb + st * STAGE_B + which * TILE_B +
                           swz((uint32_t)(row * 128 + kb * 16));
            cpasync16(dst, src);
        }
        CP_COMMIT();
    };

    issue(0, 0);
    issue(1, 1);

    const int g  = lane >> 3;
    const int lr = lane & 7;

    int stg = 0, stgNext = 2;
    for (int c = 0; c < CK; ++c) {
        if (c + 1 < CK) { CP_WAIT1(); } else { CP_WAIT0(); }
        __syncthreads();
        if (c + 2 < CK) {
            issue(c + 2, stgNext);
            if (++stgNext == NSTG) stgNext = 0;
        }

        const uint32_t tb = sb + stg * STAGE_B;
        if (++stg == NSTG) stg = 0;

        #pragma unroll
        for (int kss = 0; kss < 4; ++kss) {
            const int ks = (kss + wm) & 3;
            const int kByte = ks * 32 + (g >> 1) * 16;
            uint32_t ah[2][4], al[2][4], bh[2][4], bl[2][4];
            #pragma unroll
            for (int jj = 0; jj < 2; ++jj) {
                int row = wn * 32 + jj * 16 + (g & 1) * 8 + lr;
                uint32_t off = swz((uint32_t)(row * 128 + kByte));
                ldsm4(bh[jj], tb + 2 * TILE_B + off);
                if (passes == 3) ldsm4(bl[jj], tb + 3 * TILE_B + off);
            }
            #pragma unroll
            for (int i = 0; i < 2; ++i) {
                int row = wm * 32 + i * 16 + (g & 1) * 8 + lr;
                uint32_t off = swz((uint32_t)(row * 128 + kByte));
                ldsm4(ah[i], tb + off);
                if (passes >= 2) ldsm4(al[i], tb + TILE_B + off);
            }
            #pragma unroll
            for (int i = 0; i < 2; ++i)
                #pragma unroll
                for (int jj = 0; jj < 2; ++jj) {
                    mma16816(acc[i][2*jj],   ah[i], bh[jj][0], bh[jj][2]);
                    mma16816(acc[i][2*jj+1], ah[i], bh[jj][1], bh[jj][3]);
                }
            if (passes == 3) {
                #pragma unroll
                for (int i = 0; i < 2; ++i)
                    #pragma unroll
                    for (int jj = 0; jj < 2; ++jj) {
                        mma16816(acc[i][2*jj],   ah[i], bl[jj][0], bl[jj][2]);
                        mma16816(acc[i][2*jj+1], ah[i], bl[jj][1], bl[jj][3]);
                    }
            }
            if (passes >= 2) {
                #pragma unroll
                for (int i = 0; i < 2; ++i)
                    #pragma unroll
                    for (int jj = 0; jj < 2; ++jj) {
                        mma16816(acc[i][2*jj],   al[i], bh[jj][0], bh[jj][2]);
                        mma16816(acc[i][2*jj+1], al[i], bh[jj][1], bh[jj][3]);
                    }
            }
        }
    }

    float* Cp = C + (size_t)dir * (size_t)M * N;
    #pragma unroll
    for (int i = 0; i < 2; ++i) {
        int r0 = mBase + wm * 32 + i * 16 + (lane >> 2);
        #pragma unroll
        for (int j = 0; j < 4; ++j) {
            int col = nBase + wn * 32 + j * 8 + (lane & 3) * 2;
            float2 v0 = make_float2(acc[i][j][0], acc[i][j][1]);
            float2 v1 = make_float2(acc[i][j][2], acc[i][j][3]);
            *reinterpret_cast<float2*>(Cp + (size_t)r0 * N + col)       = v0;
            *reinterpret_cast<float2*>(Cp + (size_t)(r0 + 8) * N + col) = v1;
        }
    }
}

// ================= layernorm -> bf16 =================
__device__ __forceinline__ float block_sum(float v, float* sh) {
    int lane = threadIdx.x & 31, w = threadIdx.x >> 5;
    #pragma unroll
    for (int o = 16; o; o >>= 1) v += __shfl_xor_sync(0xffffffffu, v, o);
    if (lane == 0) sh[w] = v;
    __syncthreads();
    if (w == 0) {
        float x = (lane < 8) ? sh[lane] : 0.f;
        #pragma unroll
        for (int o = 4; o; o >>= 1) x += __shfl_xor_sync(0xffffffffu, x, o);
        if (lane == 0) sh[0] = x;
    }
    __syncthreads();
    float r = sh[0];
    __syncthreads();
    return r;
}

__global__ __launch_bounds__(256) void ln_kernel(
    const float* __restrict__ x, const float* __restrict__ gam,
    const float* __restrict__ bet, bf16* __restrict__ xh)
{
    __shared__ float sh[8];
    int tok = blockIdx.x;
    const float* xr = x + (size_t)tok * DM;
    int tid = threadIdx.x;
    float v0 = xr[tid], v1 = xr[tid + 256], v2 = xr[tid + 512];
    float s = block_sum(v0 + v1 + v2, sh);
    float mu = s * (1.0f / DM);
    float d0 = v0 - mu, d1 = v1 - mu, d2 = v2 - mu;
    float vs = block_sum(d0 * d0 + d1 * d1 + d2 * d2, sh);
    float inv = rsqrtf(vs * (1.0f / DM) + 1e-5f);
    size_t ob = (size_t)tok * DM;
    #pragma unroll
    for (int p = 0; p < 3; ++p) {
        int i = tid + p * 256;
        float d = (p == 0 ? d0 : p == 1 ? d1 : d2);
        xh[ob + i] = __float2bfloat16(d * inv * gam[i] + bet[i]);
    }
}

// ================= weight transpose + bf16 =================
__global__ void wsplit_kernel(const float* __restrict__ w0, const float* __restrict__ w1,
                              bf16* __restrict__ th, int K, int N)
{
    __shared__ float t[32][33];
    int dir = blockIdx.z;
    const float* w = dir ? w1 : w0;
    int k0 = blockIdx.y * 32, n0 = blockIdx.x * 32;
    int tx = threadIdx.x, ty = threadIdx.y;
    #pragma unroll
    for (int i = 0; i < 4; ++i)
        t[ty + 8 * i][tx] = w[(size_t)(k0 + ty + 8 * i) * N + n0 + tx];
    __syncthreads();
    bf16* thp = th + (size_t)dir * N * K;
    #pragma unroll
    for (int i = 0; i < 4; ++i) {
        int n = n0 + ty + 8 * i, k = k0 + tx;
        thp[(size_t)n * K + k] = __float2bfloat16(t[tx][ty + 8 * i]);
    }
}

// ===== FUSED: conv+SiLU -> xc ; bcdt -> (B,C) ; dt = softplus =============
// Warp per (dir, token). xw staged in smem per 256-k chunk (as old bcdt).
__global__ __launch_bounds__(256) void fused_cbd_kernel(
    const float* __restrict__ xz,
    const float* __restrict__ cw0, const float* __restrict__ cw1,
    const float* __restrict__ cb0, const float* __restrict__ cb1,
    const float* __restrict__ xw0, const float* __restrict__ xw1,
    const float* __restrict__ dtw0, const float* __restrict__ dtw1,
    const float* __restrict__ dtb0, const float* __restrict__ dtb1,
    float* __restrict__ xc, float2* __restrict__ bc, float* __restrict__ dt)
{
    __shared__ float sw[256 * NX];
    int dir  = blockIdx.z;
    int warp = threadIdx.x >> 5;
    int lane = threadIdx.x & 31;
    int tok  = blockIdx.x * 8 + warp;
    int l    = tok & (SEQ - 1);
    const float* xw = dir ? xw1 : xw0;
    const float* cw = dir ? cw1 : cw0;
    const float* cb = dir ? cb1 : cb0;
    const float* xzp = xz + (size_t)dir * TOK * DI2 + (size_t)tok * DI2;
    float* xcp = xc + ((size_t)dir * TOK + tok) * DI;

    bool v0 = (l >= 3), v1 = (l >= 2), v2 = (l >= 1);
    const float4 f40 = make_float4(0.f, 0.f, 0.f, 0.f);

    float acc = 0.f, acc32 = 0.f;
    for (int kc = 0; kc < DI; kc += 256) {
        __syncthreads();
        for (int i = threadIdx.x; i < 256 * NX; i += 256)
            sw[i] = xw[(size_t)kc * NX + i];
        __syncthreads();
        #pragma unroll 2
        for (int k = 0; k < 256; k += 4) {
            int kk = kc + k + lane * 4;
            // 8 lanes x 4 ch = 32 ch... NO: keep original mapping: each lane
            // walks the whole 256 chunk in steps of 4 (k is the walk var).
            kk = kc + k;
            // conv inputs: rows tok-3..tok, channels kk..kk+3 (per-lane offset below)
            // original bcdt used per-lane identical walk with float4 at xr+kc+k.
            float4 x3 = *reinterpret_cast<const float4*>(xzp + kk);
            float4 x2 = v2 ? *reinterpret_cast<const float4*>(xzp - DI2 + kk)     : f40;
            float4 x1 = v1 ? *reinterpret_cast<const float4*>(xzp - 2 * DI2 + kk) : f40;
            float4 x0 = v0 ? *reinterpret_cast<const float4*>(xzp - 3 * DI2 + kk) : f40;
            float4 cbv = *reinterpret_cast<const float4*>(cb + kk);
            float4 wa = *reinterpret_cast<const float4*>(cw + (size_t)(kk + 0) * 4);
            float4 wb = *reinterpret_cast<const float4*>(cw + (size_t)(kk + 1) * 4);
            float4 wc = *reinterpret_cast<const float4*>(cw + (size_t)(kk + 2) * 4);
            float4 wd = *reinterpret_cast<const float4*>(cw + (size_t)(kk + 3) * 4);
            float4 xv;
            {
                float a0 = cbv.x;
                a0 = fmaf(wa.x, x0.x, a0); a0 = fmaf(wa.y, x1.x, a0);
                a0 = fmaf(wa.z, x2.x, a0); a0 = fmaf(wa.w, x3.x, a0);
                xv.x = a0 * (1.f / (1.f + __expf(-a0)));
                float a1 = cbv.y;
                a1 = fmaf(wb.x, x0.y, a1); a1 = fmaf(wb.y, x1.y, a1);
                a1 = fmaf(wb.z, x2.y, a1); a1 = fmaf(wb.w, x3.y, a1);
                xv.y = a1 * (1.f / (1.f + __expf(-a1)));
                float a2 = cbv.z;
                a2 = fmaf(wc.x, x0.z, a2); a2 = fmaf(wc.y, x1.z, a2);
                a2 = fmaf(wc.z, x2.z, a2); a2 = fmaf(wc.w, x3.z, a2);
                xv.z = a2 * (1.f / (1.f + __expf(-a2)));
                float a3 = cbv.w;
                a3 = fmaf(wd.x, x0.w, a3); a3 = fmaf(wd.y, x1.w, a3);
                a3 = fmaf(wd.z, x2.w, a3); a3 = fmaf(wd.w, x3.w, a3);
                xv.w = a3 * (1.f / (1.f + __expf(-a3)));
            }
            *reinterpret_cast<float4*>(xcp + kk) = xv;
            const float* wr = sw + k * NX;
            acc = fmaf(xv.x, wr[lane],          acc);
            acc = fmaf(xv.y, wr[NX + lane],     acc);
            acc = fmaf(xv.z, wr[2 * NX + lane], acc);
            acc = fmaf(xv.w, wr[3 * NX + lane], acc);
            if (lane == 0) {
                acc32 = fmaf(xv.x, wr[32],          acc32);
                acc32 = fmaf(xv.y, wr[NX + 32],     acc32);
                acc32 = fmaf(xv.z, wr[2 * NX + 32], acc32);
                acc32 = fmaf(xv.w, wr[3 * NX + 32], acc32);
            }
        }
    }
    const unsigned full = 0xffffffffu;
    float dr  = __shfl_sync(full, acc, 0);
    float Bs  = __shfl_sync(full, acc, (lane & 15) + 1);
    float Cs  = __shfl_sync(full, acc, (lane & 15) + 17);
    float c15 = __shfl_sync(full, acc32, 0);
    if ((lane & 15) == 15) Cs = c15;
    if (lane < 16)
        bc[((size_t)dir * TOK + tok) * NSTATE + lane] = make_float2(Bs, Cs);

    // dt = softplus(dr * dtw + dtb)
    const float* dtw = dir ? dtw1 : dtw0;
    const float* dtb = dir ? dtb1 : dtb0;
    float* dtp = dt + ((size_t)dir * TOK + tok) * DI;
    for (int d = lane; d < DI; d += 32) {
        float pre = fmaf(dr, dtw[d], dtb[d]);
        float dtv = (pre > 20.f) ? pre : log1pf(expf(pre));
        dtp[d] = dtv;
    }
}

// ===== parallel scan: 4 channels/warp, 2 states/lane, CHB=32 ===============
#define TC  64
#define CHB 32

// phase 1: per-chunk (P = prod a, Hloc)
__global__ __launch_bounds__(256) void scan_p1(
    const float* __restrict__ dt, const float* __restrict__ xc,
    const float2* __restrict__ bc,
    const float* __restrict__ Alog0, const float* __restrict__ Alog1,
    float* __restrict__ P, float* __restrict__ Hl)
{
    extern __shared__ __align__(16) char smem[];
    float*  s_dt = (float*)smem;
    float*  s_xc = (float*)(smem + 16384);
    float2* s_bc = (float2*)(smem + 32768);

    int tid  = threadIdx.x;
    int w    = tid >> 5;
    int lane = tid & 31;
    int dirb = blockIdx.y;
    int dir  = dirb >> 1;
    int b    = dirb & 1;
    int cch  = blockIdx.z;
    int grp  = lane >> 3;
    int li   = lane & 7;
    int s0   = li * 2;
    int dloc = w * 4 + grp;
    int d0   = blockIdx.x * CHB;
    int d    = d0 + dloc;

    const float* Alog = dir ? Alog1 : Alog0;
    float a0 = fminf(fmaxf(Alog[d * NSTATE + s0],     -6.f), 6.f);
    float a1 = fminf(fmaxf(Alog[d * NSTATE + s0 + 1], -6.f), 6.f);
    float Av0 = -__expf(a0), Av1 = -__expf(a1);

    size_t tokBase = (size_t)dir * TOK + (size_t)b * SEQ + (size_t)cch * LCH;
    const float* dtg = dt + tokBase * DI + d0;
    const float* xcg = xc + tokBase * DI + d0;
    const float2* bcg = bc + tokBase * NSTATE;

    auto issue = [&](int c, int buf) {
        #pragma unroll
        for (int p = 0; p < 2; ++p) {
            int idx = tid + 256 * p;
            int t2 = idx >> 3, q2 = idx & 7;
            size_t rowT = (size_t)(c * TC + t2);
            cpasync16(s2u(&s_dt[(buf * TC + t2) * CHB + q2 * 4]), dtg + rowT * DI + q2 * 4);
            cpasync16(s2u(&s_xc[(buf * TC + t2) * CHB + q2 * 4]), xcg + rowT * DI + q2 * 4);
            cpasync16(s2u(&s_bc[(buf * TC + t2) * NSTATE + q2 * 2]), bcg + rowT * NSTATE + q2 * 2);
        }
        CP_COMMIT();
    };

    issue(0, 0);
    const int NCH = LCH / TC;
    float h0 = 0.f, h1 = 0.f, cum0 = 1.f, cum1 = 1.f;
    int buf = 0;
    for (int c = 0; c < NCH; ++c) {
        if (c + 1 < NCH) { issue(c + 1, buf ^ 1); CP_WAIT1(); }
        else             { CP_WAIT0(); }
        __syncthreads();
        #pragma unroll 4
        for (int tt = 0; tt < TC; ++tt) {
            float dtc = s_dt[(buf * TC + tt) * CHB + dloc];
            float xcc = s_xc[(buf * TC + tt) * CHB + dloc];
            float4 bq = *reinterpret_cast<const float4*>(&s_bc[(buf * TC + tt) * NSTATE + s0]);
            float u  = dtc * xcc;
            float e0 = __expf(dtc * Av0);
            float e1 = __expf(dtc * Av1);
            h0 = fmaf(e0, h0, u * bq.x);
            h1 = fmaf(e1, h1, u * bq.z);
            cum0 *= e0;
            cum1 *= e1;
        }
        __syncthreads();
        buf ^= 1;
    }
    size_t idx = ((size_t)dirb * NC + cch) * (DI * NSTATE) + (size_t)d * NSTATE + s0;
    *reinterpret_cast<float2*>(&P[idx])  = make_float2(cum0, cum1);
    *reinterpret_cast<float2*>(&Hl[idx]) = make_float2(h0, h1);
}

// phase 2a: sequential prefix over chunks
__global__ __launch_bounds__(256) void scan_pre(
    const float* __restrict__ P, const float* __restrict__ Hl,
    float* __restrict__ Hin)
{
    int j = blockIdx.x * blockDim.x + threadIdx.x;
    int dirb = j / (DI * NSTATE);
    int r    = j - dirb * (DI * NSTATE);
    float acc = 0.f;
    for (int c = 0; c < NC; ++c) {
        size_t idx = ((size_t)dirb * NC + c) * (DI * NSTATE) + r;
        Hin[idx] = acc;
        acc = P[idx] * acc + Hl[idx];
    }
}

// phase 2b: true scan per chunk from Hin + fused gate (bf16)
__global__ __launch_bounds__(256) void scan_p2(
    const float* __restrict__ dt, const float* __restrict__ xc,
    const float* __restrict__ xz, const float2* __restrict__ bc,
    const float* __restrict__ Alog0, const float* __restrict__ Alog1,
    const float* __restrict__ Dp0, const float* __restrict__ Dp1,
    const float* __restrict__ Hin, bf16* __restrict__ gh)
{
    extern __shared__ __align__(16) char smem[];
    float*  s_dt = (float*)smem;
    float*  s_xc = (float*)(smem + 16384);
    float*  s_z  = (float*)(smem + 32768);
    float2* s_bc = (float2*)(smem + 49152);
    bf16*   sgh  = (bf16*)(smem + 65536);

    const unsigned full = 0xffffffffu;
    int tid  = threadIdx.x;
    int w    = tid >> 5;
    int lane = tid & 31;
    int dirb = blockIdx.y;
    int dir  = dirb >> 1;
    int b    = dirb & 1;
    int cch  = blockIdx.z;
    int grp  = lane >> 3;
    int li   = lane & 7;
    int s0   = li * 2;
    int dloc = w * 4 + grp;
    int d0   = blockIdx.x * CHB;
    int d    = d0 + dloc;

    const float* Alog = dir ? Alog1 : Alog0;
    float a0 = fminf(fmaxf(Alog[d * NSTATE + s0],     -6.f), 6.f);
    float a1 = fminf(fmaxf(Alog[d * NSTATE + s0 + 1], -6.f), 6.f);
    float Av0 = -__expf(a0), Av1 = -__expf(a1);
    float Dv = (dir ? Dp1 : Dp0)[d];
    bool st = (li == 0);

    size_t tokBase = (size_t)dir * TOK + (size_t)b * SEQ + (size_t)cch * LCH;
    const float* dtg = dt + tokBase * DI + d0;
    const float* xcg = xc + tokBase * DI + d0;
    const float* zg  = xz + tokBase * DI2 + DI + d0;
    const float2* bcg = bc + tokBase * NSTATE;

    auto issue = [&](int c, int buf) {
        #pragma unroll
        for (int p = 0; p < 2; ++p) {
            int idx = tid + 256 * p;
            int t2 = idx >> 3, q2 = idx & 7;
            size_t rowT = (size_t)(c * TC + t2);
            cpasync16(s2u(&s_dt[(buf * TC + t2) * CHB + q2 * 4]), dtg + rowT * DI  + q2 * 4);
            cpasync16(s2u(&s_xc[(buf * TC + t2) * CHB + q2 * 4]), xcg + rowT * DI  + q2 * 4);
            cpasync16(s2u(&s_z [(buf * TC + t2) * CHB + q2 * 4]), zg  + rowT * DI2 + q2 * 4);
            cpasync16(s2u(&s_bc[(buf * TC + t2) * NSTATE + q2 * 2]), bcg + rowT * NSTATE + q2 * 2);
        }
        CP_COMMIT();
    };

    issue(0, 0);

    float2 hin = *reinterpret_cast<const float2*>(
        &Hin[((size_t)dirb * NC + cch) * (DI * NSTATE) + (size_t)d * NSTATE + s0]);
    float h0 = hin.x, h1 = hin.y;

    const int NCH = LCH / TC;
    int buf = 0;
    for (int c = 0; c < NCH; ++c) {
        if (c + 1 < NCH) { issue(c + 1, buf ^ 1); CP_WAIT1(); }
        else             { CP_WAIT0(); }
        __syncthreads();

        #pragma unroll 4
        for (int tt = 0; tt < TC; ++tt) {
            float dtc = s_dt[(buf * TC + tt) * CHB + dloc];
            float xcc = s_xc[(buf * TC + tt) * CHB + dloc];
            float4 bq = *reinterpret_cast<const float4*>(&s_bc[(buf * TC + tt) * NSTATE + s0]);
            float u  = dtc * xcc;
            float e0 = __expf(dtc * Av0);
            float e1 = __expf(dtc * Av1);
            h0 = fmaf(e0, h0, u * bq.x);
            h1 = fmaf(e1, h1, u * bq.z);
            float p = fmaf(h1, bq.w, h0 * bq.y);
            p += __shfl_xor_sync(full, p, 4);
            p += __shfl_xor_sync(full, p, 2);
            p += __shfl_xor_sync(full, p, 1);
            if (st) {
                float zc = s_z[(buf * TC + tt) * CHB + dloc];
                float y  = fmaf(xcc, Dv, p);
                float sz = zc / (1.f + __expf(-zc));
                sgh[tt * CHB + dloc] = __float2bfloat16(y * sz);
            }
        }
        __syncthreads();
        {
            int tl0 = tid >> 5;
            int dc  = tid & 31;
            #pragma unroll
            for (int p8 = 0; p8 < 8; ++p8) {
                int tl = p8 * 8 + tl0;
                size_t go = (tokBase + (size_t)c * TC + tl) * DI + d0 + dc;
                gh[go] = sgh[tl * CHB + dc];
            }
        }
        buf ^= 1;
    }
}

// ================= combine =================
__global__ __launch_bounds__(256) void combine_kernel(
    const float* __restrict__ x, const float* __restrict__ alpha,
    const float* __restrict__ yp, float* __restrict__ out)
{
    int idx = blockIdx.x * blockDim.x + threadIdx.x;
    if (idx >= TOK * DM) return;
    int tok = idx / DM;
    int m   = idx - tok * DM;
    float a = 1.f / (1.f + __expf(-alpha[0]));
    int tokb = tok ^ (SEQ - 1);
    float yf = yp[idx];
    float yb = yp[(size_t)TOK * DM + (size_t)tokb * DM + m];
    out[idx] = fmaf(a, yf, fmaf(1.f - a, yb, x[idx]));
}

// ================= launch =================
extern "C" void kernel_launch(void* const* d_in, const int* in_sizes, int n_in,
                              void* d_out, int out_size)
{
    const float* x     = (const float*)d_in[0];
    const float* ln_g  = (const float*)d_in[1];
    const float* ln_b  = (const float*)d_in[2];
    const float* alpha = (const float*)d_in[3];
    const float* f_inw  = (const float*)d_in[4];
    const float* f_cw   = (const float*)d_in[5];
    const float* f_cb   = (const float*)d_in[6];
    const float* f_xw   = (const float*)d_in[7];
    const float* f_dtw  = (const float*)d_in[8];
    const float* f_dtb  = (const float*)d_in[9];
    const float* f_Alog = (const float*)d_in[10];
    const float* f_D    = (const float*)d_in[11];
    const float* f_outw = (const float*)d_in[12];
    const float* b_inw  = (const float*)d_in[13];
    const float* b_cw   = (const float*)d_in[14];
    const float* b_cb   = (const float*)d_in[15];
    const float* b_xw   = (const float*)d_in[16];
    const float* b_dtw  = (const float*)d_in[17];
    const float* b_dtb  = (const float*)d_in[18];
    const float* b_Alog = (const float*)d_in[19];
    const float* b_D    = (const float*)d_in[20];
    const float* b_outw = (const float*)d_in[21];
    float* out = (float*)d_out;

    bf16 *xnh, *winh, *wouth, *gh;
    float *xz, *xc, *dtb_, *yp, *Pp, *Hlp, *Hinp;
    float2 *bc;
    cudaGetSymbolAddress((void**)&xnh,   g_xn_h);
    cudaGetSymbolAddress((void**)&winh,  g_win_h);
    cudaGetSymbolAddress((void**)&wouth, g_wout_h);
    cudaGetSymbolAddress((void**)&gh,    g_gh);
    cudaGetSymbolAddress((void**)&xz,    g_xz);
    cudaGetSymbolAddress((void**)&xc,    g_xc);
    cudaGetSymbolAddress((void**)&bc,    g_bc);
    cudaGetSymbolAddress((void**)&dtb_,  g_dt);
    cudaGetSymbolAddress((void**)&yp,    g_yp);
    cudaGetSymbolAddress((void**)&Pp,    g_P);
    cudaGetSymbolAddress((void**)&Hlp,   g_Hl);
    cudaGetSymbolAddress((void**)&Hinp,  g_Hin);

    const int smemGemm = NSTG * STAGE_B;
    cudaFuncSetAttribute(mma_gemm, cudaFuncAttributeMaxDynamicSharedMemorySize, smemGemm);
    const int smemP1 = 48 * 1024;
    const int smemP2 = 70 * 1024;
    cudaFuncSetAttribute(scan_p1, cudaFuncAttributeMaxDynamicSharedMemorySize, smemP1);
    cudaFuncSetAttribute(scan_p2, cudaFuncAttributeMaxDynamicSharedMemorySize, smemP2);

    // 1) layernorm -> bf16
    ln_kernel<<<TOK, 256>>>(x, ln_g, ln_b, xnh);

    // 2) weight transpose + bf16
    wsplit_kernel<<<dim3(DI2 / 32, DM / 32, 2), dim3(32, 8)>>>(
        f_inw, b_inw, winh, DM, DI2);
    wsplit_kernel<<<dim3(DM / 32, DI / 32, 2), dim3(32, 8)>>>(
        f_outw, b_outw, wouth, DI, DM);

    // 3) in-proj GEMM (1-pass bf16)
    mma_gemm<<<dim3(DI2 / 128, TOK / 128, 2), 512, smemGemm>>>(
        xnh, xnh, winh, winh, xz, TOK, DI2, DM, 0, 1, 1);

    // 4) FUSED conv+SiLU + bcdt + dt
    fused_cbd_kernel<<<dim3(TOK / 8, 1, 2), 256>>>(
        xz, f_cw, b_cw, f_cb, b_cb, f_xw, b_xw,
        f_dtw, b_dtw, f_dtb, b_dtb, xc, bc, dtb_);

    // 5) parallel scan: phase 1, prefix, phase 2 (+gate)
    scan_p1<<<dim3(DI / CHB, 4, NC), 256, smemP1>>>(
        dtb_, xc, bc, f_Alog, b_Alog, Pp, Hlp);
    scan_pre<<<(4 * DI * NSTATE) / 256, 256>>>(Pp, Hlp, Hinp);
    scan_p2<<<dim3(DI / CHB, 4, NC), 256, smemP2>>>(
        dtb_, xc, xz, bc, f_Alog, b_Alog, f_D, b_D, Hinp, gh);

    // 6) out-proj GEMM (1-pass bf16)
    mma_gemm<<<dim3(DM / 128, TOK / 128, 2), 512, smemGemm>>>(
        gh, gh, wouth, wouth, yp, TOK, DM, DI, 1, 0, 1);

    // 7) combine + residual
    combine_kernel<<<(TOK * DM) / 256, 256>>>(x, alpha, yp, out);
}

// round 17
// speedup vs baseline: 1.4615x; 1.4615x over previous
#include <cuda_runtime.h>
#include <cuda_bf16.h>
#include <cstdint>

// ---------------- problem constants ----------------
#define BATCH   2
#define SEQ     2048
#define TOK     (BATCH * SEQ)        // 4096
#define DM      768                  // d_model
#define DI      1536                 // d_inner
#define DI2     (2 * DI)             // 3072
#define NSTATE  16
#define NX      33                   // 1 + 2*NSTATE
#define DCONV   4
#define NC      16                   // scan chunks
#define LCH     (SEQ / NC)           // 128 timesteps per chunk

typedef __nv_bfloat16 bf16;

// ---------------- scratch (static device globals) --------
__device__ __align__(16) bf16  g_xn_h [TOK * DM];
__device__ __align__(16) bf16  g_win_h[2ll * DI2 * DM];
__device__ __align__(16) bf16  g_wout_h[2ll * DM * DI];
__device__ __align__(16) bf16  g_gh [2ll * TOK * DI];
__device__ __align__(16) float  g_xz   [2ll * TOK * DI2];
__device__ __align__(16) float  g_xc   [2ll * TOK * DI];
__device__ __align__(16) float2 g_bc [2ll * TOK * NSTATE];
__device__ __align__(16) float  g_dt   [2ll * TOK * DI];
__device__ float  g_yp   [2ll * TOK * DM];
// parallel-scan intermediates: [dirb(4)][NC][DI*NSTATE]
__device__ __align__(16) float g_P  [4ll * NC * DI * NSTATE];
__device__ __align__(16) float g_Hl [4ll * NC * DI * NSTATE];
__device__ __align__(16) float g_Hin[4ll * NC * DI * NSTATE];

// ================= helpers =================
__device__ __forceinline__ uint32_t s2u(const void* p) {
    uint32_t a;
    asm("{ .reg .u64 t; cvta.to.shared.u64 t, %1; cvt.u32.u64 %0, t; }"
        : "=r"(a) : "l"(p));
    return a;
}
__device__ __forceinline__ uint32_t swz(uint32_t off) {
    return off ^ ((off >> 3) & 0x70);
}
__device__ __forceinline__ void cpasync16(uint32_t dst, const void* src) {
    asm volatile("cp.async.cg.shared.global [%0], [%1], 16;" :: "r"(dst), "l"(src) : "memory");
}
#define CP_COMMIT() asm volatile("cp.async.commit_group;" ::: "memory")
#define CP_WAIT0()  asm volatile("cp.async.wait_group 0;" ::: "memory")
#define CP_WAIT1()  asm volatile("cp.async.wait_group 1;" ::: "memory")

__device__ __forceinline__ void ldsm4(uint32_t* r, uint32_t addr) {
    asm volatile("ldmatrix.sync.aligned.m8n8.x4.shared.b16 {%0,%1,%2,%3}, [%4];"
                 : "=r"(r[0]), "=r"(r[1]), "=r"(r[2]), "=r"(r[3]) : "r"(addr));
}
__device__ __forceinline__ void mma16816(float* c, const uint32_t* a,
                                         uint32_t b0, uint32_t b1) {
    asm volatile(
        "mma.sync.aligned.m16n8k16.row.col.f32.bf16.bf16.f32 "
        "{%0,%1,%2,%3}, {%4,%5,%6,%7}, {%8,%9}, {%0,%1,%2,%3};"
        : "+f"(c[0]), "+f"(c[1]), "+f"(c[2]), "+f"(c[3])
        : "r"(a[0]), "r"(a[1]), "r"(a[2]), "r"(a[3]), "r"(b0), "r"(b1));
}

// ================= mma.sync GEMM (unchanged from R15) ======================
#define BK 64
#define TILE_B 16384
#define STAGE_B (4 * TILE_B)
#define NSTG 3

__global__ __launch_bounds__(512, 1)
void mma_gemm(const bf16* __restrict__ Ah, const bf16* __restrict__ Al,
              const bf16* __restrict__ Bh, const bf16* __restrict__ Bl,
              float* __restrict__ C, int M, int N, int K, int aPerDir, int flipA,
              int passes)
{
    extern __shared__ __align__(1024) char smem[];
    const int dir   = blockIdx.z;
    const int mBase = blockIdx.y * 128;
    const int nBase = blockIdx.x * 128;
    const uint32_t sb = s2u(smem);
    const int tid = threadIdx.x, wid = tid >> 5, lane = tid & 31;
    const int wm = wid & 3, wn = wid >> 2;

    const bf16* Ahp = Ah + (aPerDir ? (size_t)dir * M * K : 0);
    const bf16* Alp = Al + (aPerDir ? (size_t)dir * M * K : 0);
    const bf16* Bhp = Bh + (size_t)dir * (size_t)N * K;
    const bf16* Blp = Bl + (size_t)dir * (size_t)N * K;

    const int CK = K / BK;

    float acc[2][4][4];
    #pragma unroll
    for (int i = 0; i < 2; i++)
        #pragma unroll
        for (int j = 0; j < 4; j++)
            #pragma unroll
            for (int q = 0; q < 4; q++) acc[i][j][q] = 0.f;

    auto issue = [&](int c, int st) {
        const int k0 = c * BK;
        #pragma unroll
        for (int i = 0; i < 8; ++i) {
            int q     = tid + 512 * i;
            int which = q >> 10;
            if (which == 1 && passes < 2) continue;
            if (which == 3 && passes < 3) continue;
            int t     = q & 1023;
            int row   = t >> 3;
            int kb    = t & 7;
            const bf16* src;
            if (which < 2) {
                int grow = mBase + row;
                if (flipA && dir) grow ^= (SEQ - 1);
                src = (which ? Alp : Ahp) + (size_t)grow * K + k0 + kb * 8;
            } else {
                src = ((which == 3) ? Blp : Bhp) + (size_t)(nBase + row) * K + k0 + kb * 8;
            }
            uint32_t dst = sb + st * STAGE_B + which * TILE_B +
                           swz((uint32_t)(row * 128 + kb * 16));
            cpasync16(dst, src);
        }
        CP_COMMIT();
    };

    issue(0, 0);
    issue(1, 1);

    const int g  = lane >> 3;
    const int lr = lane & 7;

    int stg = 0, stgNext = 2;
    for (int c = 0; c < CK; ++c) {
        if (c + 1 < CK) { CP_WAIT1(); } else { CP_WAIT0(); }
        __syncthreads();
        if (c + 2 < CK) {
            issue(c + 2, stgNext);
            if (++stgNext == NSTG) stgNext = 0;
        }

        const uint32_t tb = sb + stg * STAGE_B;
        if (++stg == NSTG) stg = 0;

        #pragma unroll
        for (int kss = 0; kss < 4; ++kss) {
            const int ks = (kss + wm) & 3;
            const int kByte = ks * 32 + (g >> 1) * 16;
            uint32_t ah[2][4], al[2][4], bh[2][4], bl[2][4];
            #pragma unroll
            for (int jj = 0; jj < 2; ++jj) {
                int row = wn * 32 + jj * 16 + (g & 1) * 8 + lr;
                uint32_t off = swz((uint32_t)(row * 128 + kByte));
                ldsm4(bh[jj], tb + 2 * TILE_B + off);
                if (passes == 3) ldsm4(bl[jj], tb + 3 * TILE_B + off);
            }
            #pragma unroll
            for (int i = 0; i < 2; ++i) {
                int row = wm * 32 + i * 16 + (g & 1) * 8 + lr;
                uint32_t off = swz((uint32_t)(row * 128 + kByte));
                ldsm4(ah[i], tb + off);
                if (passes >= 2) ldsm4(al[i], tb + TILE_B + off);
            }
            #pragma unroll
            for (int i = 0; i < 2; ++i)
                #pragma unroll
                for (int jj = 0; jj < 2; ++jj) {
                    mma16816(acc[i][2*jj],   ah[i], bh[jj][0], bh[jj][2]);
                    mma16816(acc[i][2*jj+1], ah[i], bh[jj][1], bh[jj][3]);
                }
            if (passes == 3) {
                #pragma unroll
                for (int i = 0; i < 2; ++i)
                    #pragma unroll
                    for (int jj = 0; jj < 2; ++jj) {
                        mma16816(acc[i][2*jj],   ah[i], bl[jj][0], bl[jj][2]);
                        mma16816(acc[i][2*jj+1], ah[i], bl[jj][1], bl[jj][3]);
                    }
            }
            if (passes >= 2) {
                #pragma unroll
                for (int i = 0; i < 2; ++i)
                    #pragma unroll
                    for (int jj = 0; jj < 2; ++jj) {
                        mma16816(acc[i][2*jj],   al[i], bh[jj][0], bh[jj][2]);
                        mma16816(acc[i][2*jj+1], al[i], bh[jj][1], bh[jj][3]);
                    }
            }
        }
    }

    float* Cp = C + (size_t)dir * (size_t)M * N;
    #pragma unroll
    for (int i = 0; i < 2; ++i) {
        int r0 = mBase + wm * 32 + i * 16 + (lane >> 2);
        #pragma unroll
        for (int j = 0; j < 4; ++j) {
            int col = nBase + wn * 32 + j * 8 + (lane & 3) * 2;
            float2 v0 = make_float2(acc[i][j][0], acc[i][j][1]);
            float2 v1 = make_float2(acc[i][j][2], acc[i][j][3]);
            *reinterpret_cast<float2*>(Cp + (size_t)r0 * N + col)       = v0;
            *reinterpret_cast<float2*>(Cp + (size_t)(r0 + 8) * N + col) = v1;
        }
    }
}

// ================= layernorm -> bf16 =================
__device__ __forceinline__ float block_sum(float v, float* sh) {
    int lane = threadIdx.x & 31, w = threadIdx.x >> 5;
    #pragma unroll
    for (int o = 16; o; o >>= 1) v += __shfl_xor_sync(0xffffffffu, v, o);
    if (lane == 0) sh[w] = v;
    __syncthreads();
    if (w == 0) {
        float x = (lane < 8) ? sh[lane] : 0.f;
        #pragma unroll
        for (int o = 4; o; o >>= 1) x += __shfl_xor_sync(0xffffffffu, x, o);
        if (lane == 0) sh[0] = x;
    }
    __syncthreads();
    float r = sh[0];
    __syncthreads();
    return r;
}

__global__ __launch_bounds__(256) void ln_kernel(
    const float* __restrict__ x, const float* __restrict__ gam,
    const float* __restrict__ bet, bf16* __restrict__ xh)
{
    __shared__ float sh[8];
    int tok = blockIdx.x;
    const float* xr = x + (size_t)tok * DM;
    int tid = threadIdx.x;
    float v0 = xr[tid], v1 = xr[tid + 256], v2 = xr[tid + 512];
    float s = block_sum(v0 + v1 + v2, sh);
    float mu = s * (1.0f / DM);
    float d0 = v0 - mu, d1 = v1 - mu, d2 = v2 - mu;
    float vs = block_sum(d0 * d0 + d1 * d1 + d2 * d2, sh);
    float inv = rsqrtf(vs * (1.0f / DM) + 1e-5f);
    size_t ob = (size_t)tok * DM;
    #pragma unroll
    for (int p = 0; p < 3; ++p) {
        int i = tid + p * 256;
        float d = (p == 0 ? d0 : p == 1 ? d1 : d2);
        xh[ob + i] = __float2bfloat16(d * inv * gam[i] + bet[i]);
    }
}

// ================= weight transpose + bf16 =================
__global__ void wsplit_kernel(const float* __restrict__ w0, const float* __restrict__ w1,
                              bf16* __restrict__ th, int K, int N)
{
    __shared__ float t[32][33];
    int dir = blockIdx.z;
    const float* w = dir ? w1 : w0;
    int k0 = blockIdx.y * 32, n0 = blockIdx.x * 32;
    int tx = threadIdx.x, ty = threadIdx.y;
    #pragma unroll
    for (int i = 0; i < 4; ++i)
        t[ty + 8 * i][tx] = w[(size_t)(k0 + ty + 8 * i) * N + n0 + tx];
    __syncthreads();
    bf16* thp = th + (size_t)dir * N * K;
    #pragma unroll
    for (int i = 0; i < 4; ++i) {
        int n = n0 + ty + 8 * i, k = k0 + tx;
        thp[(size_t)n * K + k] = __float2bfloat16(t[tx][ty + 8 * i]);
    }
}

// ================= depthwise causal conv (k=4) + bias + SiLU =================
__global__ __launch_bounds__(256) void conv_silu_kernel(
    const float* __restrict__ xz, const float* __restrict__ cw0,
    const float* __restrict__ cw1, const float* __restrict__ cb0,
    const float* __restrict__ cb1, float* __restrict__ xc)
{
    int dir = blockIdx.z;
    int idx = blockIdx.x * blockDim.x + threadIdx.x;
    if (idx >= TOK * DI) return;
    int tok = idx / DI;
    int d   = idx - tok * DI;
    int l   = tok & (SEQ - 1);
    const float* cw = (dir ? cw1 : cw0) + d * DCONV;
    float acc = (dir ? cb1 : cb0)[d];
    const float* xzp = xz + (size_t)dir * TOK * DI2 + (size_t)tok * DI2 + d;
    #pragma unroll
    for (int j = 0; j < DCONV; j++) {
        int lo = l - (DCONV - 1) + j;
        if (lo >= 0) acc = fmaf(cw[j], xzp[(long)(j - (DCONV - 1)) * DI2], acc);
    }
    float sg = 1.f / (1.f + __expf(-acc));
    xc[(size_t)dir * TOK * DI + idx] = acc * sg;
}

// ===== bcdt: xc @ xw -> packed (B,C); fused dt = softplus tail =============
__global__ __launch_bounds__(256) void bcdt_kernel(
    const float* __restrict__ xc, const float* __restrict__ xw0,
    const float* __restrict__ xw1, const float* __restrict__ dtw0,
    const float* __restrict__ dtw1, const float* __restrict__ dtb0,
    const float* __restrict__ dtb1, float2* __restrict__ bc,
    float* __restrict__ dt)
{
    __shared__ float sw[256 * NX];
    int dir  = blockIdx.z;
    int warp = threadIdx.x >> 5;
    int lane = threadIdx.x & 31;
    int tok  = blockIdx.x * 8 + warp;
    const float* xw = dir ? xw1 : xw0;
    const float* xr = xc + ((size_t)dir * TOK + tok) * DI;
    float acc = 0.f, acc32 = 0.f;
    for (int kc = 0; kc < DI; kc += 256) {
        __syncthreads();
        for (int i = threadIdx.x; i < 256 * NX; i += 256)
            sw[i] = xw[(size_t)kc * NX + i];
        __syncthreads();
        #pragma unroll 4
        for (int k = 0; k < 256; k += 4) {
            float4 xv = *reinterpret_cast<const float4*>(xr + kc + k);
            const float* wr = sw + k * NX;
            acc = fmaf(xv.x, wr[lane],          acc);
            acc = fmaf(xv.y, wr[NX + lane],     acc);
            acc = fmaf(xv.z, wr[2 * NX + lane], acc);
            acc = fmaf(xv.w, wr[3 * NX + lane], acc);
            if (lane == 0) {
                acc32 = fmaf(xv.x, wr[32],          acc32);
                acc32 = fmaf(xv.y, wr[NX + 32],     acc32);
                acc32 = fmaf(xv.z, wr[2 * NX + 32], acc32);
                acc32 = fmaf(xv.w, wr[3 * NX + 32], acc32);
            }
        }
    }
    const unsigned full = 0xffffffffu;
    float dr  = __shfl_sync(full, acc, 0);
    float Bs  = __shfl_sync(full, acc, (lane & 15) + 1);
    float Cs  = __shfl_sync(full, acc, (lane & 15) + 17);
    float c15 = __shfl_sync(full, acc32, 0);
    if ((lane & 15) == 15) Cs = c15;
    if (lane < 16)
        bc[((size_t)dir * TOK + tok) * NSTATE + lane] = make_float2(Bs, Cs);

    // fused dt = softplus(dr * dtw + dtb) (per-lane coalesced over DI)
    const float* dtw = dir ? dtw1 : dtw0;
    const float* dtb = dir ? dtb1 : dtb0;
    float* dtp = dt + ((size_t)dir * TOK + tok) * DI;
    for (int d = lane; d < DI; d += 32) {
        float pre = fmaf(dr, dtw[d], dtb[d]);
        float dtv = (pre > 20.f) ? pre : log1pf(expf(pre));
        dtp[d] = dtv;
    }
}

// ===== parallel scan: 4 channels/warp, 2 states/lane, CHB=32 ===============
#define TC  64
#define CHB 32

// phase 1: per-chunk (P = prod a, Hloc)
__global__ __launch_bounds__(256) void scan_p1(
    const float* __restrict__ dt, const float* __restrict__ xc,
    const float2* __restrict__ bc,
    const float* __restrict__ Alog0, const float* __restrict__ Alog1,
    float* __restrict__ P, float* __restrict__ Hl)
{
    extern __shared__ __align__(16) char smem[];
    float*  s_dt = (float*)smem;
    float*  s_xc = (float*)(smem + 16384);
    float2* s_bc = (float2*)(smem + 32768);

    int tid  = threadIdx.x;
    int w    = tid >> 5;
    int lane = tid & 31;
    int dirb = blockIdx.y;
    int dir  = dirb >> 1;
    int b    = dirb & 1;
    int cch  = blockIdx.z;
    int grp  = lane >> 3;
    int li   = lane & 7;
    int s0   = li * 2;
    int dloc = w * 4 + grp;
    int d0   = blockIdx.x * CHB;
    int d    = d0 + dloc;

    const float* Alog = dir ? Alog1 : Alog0;
    float a0 = fminf(fmaxf(Alog[d * NSTATE + s0],     -6.f), 6.f);
    float a1 = fminf(fmaxf(Alog[d * NSTATE + s0 + 1], -6.f), 6.f);
    float Av0 = -__expf(a0), Av1 = -__expf(a1);

    size_t tokBase = (size_t)dir * TOK + (size_t)b * SEQ + (size_t)cch * LCH;
    const float* dtg = dt + tokBase * DI + d0;
    const float* xcg = xc + tokBase * DI + d0;
    const float2* bcg = bc + tokBase * NSTATE;

    auto issue = [&](int c, int buf) {
        #pragma unroll
        for (int p = 0; p < 2; ++p) {
            int idx = tid + 256 * p;
            int t2 = idx >> 3, q2 = idx & 7;
            size_t rowT = (size_t)(c * TC + t2);
            cpasync16(s2u(&s_dt[(buf * TC + t2) * CHB + q2 * 4]), dtg + rowT * DI + q2 * 4);
            cpasync16(s2u(&s_xc[(buf * TC + t2) * CHB + q2 * 4]), xcg + rowT * DI + q2 * 4);
            cpasync16(s2u(&s_bc[(buf * TC + t2) * NSTATE + q2 * 2]), bcg + rowT * NSTATE + q2 * 2);
        }
        CP_COMMIT();
    };

    issue(0, 0);
    const int NCH = LCH / TC;
    float h0 = 0.f, h1 = 0.f, cum0 = 1.f, cum1 = 1.f;
    int buf = 0;
    for (int c = 0; c < NCH; ++c) {
        if (c + 1 < NCH) { issue(c + 1, buf ^ 1); CP_WAIT1(); }
        else             { CP_WAIT0(); }
        __syncthreads();
        #pragma unroll 4
        for (int tt = 0; tt < TC; ++tt) {
            float dtc = s_dt[(buf * TC + tt) * CHB + dloc];
            float xcc = s_xc[(buf * TC + tt) * CHB + dloc];
            float4 bq = *reinterpret_cast<const float4*>(&s_bc[(buf * TC + tt) * NSTATE + s0]);
            float u  = dtc * xcc;
            float e0 = __expf(dtc * Av0);
            float e1 = __expf(dtc * Av1);
            h0 = fmaf(e0, h0, u * bq.x);
            h1 = fmaf(e1, h1, u * bq.z);
            cum0 *= e0;
            cum1 *= e1;
        }
        __syncthreads();
        buf ^= 1;
    }
    size_t idx = ((size_t)dirb * NC + cch) * (DI * NSTATE) + (size_t)d * NSTATE + s0;
    *reinterpret_cast<float2*>(&P[idx])  = make_float2(cum0, cum1);
    *reinterpret_cast<float2*>(&Hl[idx]) = make_float2(h0, h1);
}

// phase 2a: sequential prefix over chunks
__global__ __launch_bounds__(256) void scan_pre(
    const float* __restrict__ P, const float* __restrict__ Hl,
    float* __restrict__ Hin)
{
    int j = blockIdx.x * blockDim.x + threadIdx.x;
    int dirb = j / (DI * NSTATE);
    int r    = j - dirb * (DI * NSTATE);
    float acc = 0.f;
    for (int c = 0; c < NC; ++c) {
        size_t idx = ((size_t)dirb * NC + c) * (DI * NSTATE) + r;
        Hin[idx] = acc;
        acc = P[idx] * acc + Hl[idx];
    }
}

// phase 2b: true scan per chunk from Hin + fused gate (bf16)
__global__ __launch_bounds__(256) void scan_p2(
    const float* __restrict__ dt, const float* __restrict__ xc,
    const float* __restrict__ xz, const float2* __restrict__ bc,
    const float* __restrict__ Alog0, const float* __restrict__ Alog1,
    const float* __restrict__ Dp0, const float* __restrict__ Dp1,
    const float* __restrict__ Hin, bf16* __restrict__ gh)
{
    extern __shared__ __align__(16) char smem[];
    float*  s_dt = (float*)smem;
    float*  s_xc = (float*)(smem + 16384);
    float*  s_z  = (float*)(smem + 32768);
    float2* s_bc = (float2*)(smem + 49152);
    bf16*   sgh  = (bf16*)(smem + 65536);

    const unsigned full = 0xffffffffu;
    int tid  = threadIdx.x;
    int w    = tid >> 5;
    int lane = tid & 31;
    int dirb = blockIdx.y;
    int dir  = dirb >> 1;
    int b    = dirb & 1;
    int cch  = blockIdx.z;
    int grp  = lane >> 3;
    int li   = lane & 7;
    int s0   = li * 2;
    int dloc = w * 4 + grp;
    int d0   = blockIdx.x * CHB;
    int d    = d0 + dloc;

    const float* Alog = dir ? Alog1 : Alog0;
    float a0 = fminf(fmaxf(Alog[d * NSTATE + s0],     -6.f), 6.f);
    float a1 = fminf(fmaxf(Alog[d * NSTATE + s0 + 1], -6.f), 6.f);
    float Av0 = -__expf(a0), Av1 = -__expf(a1);
    float Dv = (dir ? Dp1 : Dp0)[d];
    bool st = (li == 0);

    size_t tokBase = (size_t)dir * TOK + (size_t)b * SEQ + (size_t)cch * LCH;
    const float* dtg = dt + tokBase * DI + d0;
    const float* xcg = xc + tokBase * DI + d0;
    const float* zg  = xz + tokBase * DI2 + DI + d0;
    const float2* bcg = bc + tokBase * NSTATE;

    auto issue = [&](int c, int buf) {
        #pragma unroll
        for (int p = 0; p < 2; ++p) {
            int idx = tid + 256 * p;
            int t2 = idx >> 3, q2 = idx & 7;
            size_t rowT = (size_t)(c * TC + t2);
            cpasync16(s2u(&s_dt[(buf * TC + t2) * CHB + q2 * 4]), dtg + rowT * DI  + q2 * 4);
            cpasync16(s2u(&s_xc[(buf * TC + t2) * CHB + q2 * 4]), xcg + rowT * DI  + q2 * 4);
            cpasync16(s2u(&s_z [(buf * TC + t2) * CHB + q2 * 4]), zg  + rowT * DI2 + q2 * 4);
            cpasync16(s2u(&s_bc[(buf * TC + t2) * NSTATE + q2 * 2]), bcg + rowT * NSTATE + q2 * 2);
        }
        CP_COMMIT();
    };

    issue(0, 0);

    float2 hin = *reinterpret_cast<const float2*>(
        &Hin[((size_t)dirb * NC + cch) * (DI * NSTATE) + (size_t)d * NSTATE + s0]);
    float h0 = hin.x, h1 = hin.y;

    const int NCH = LCH / TC;
    int buf = 0;
    for (int c = 0; c < NCH; ++c) {
        if (c + 1 < NCH) { issue(c + 1, buf ^ 1); CP_WAIT1(); }
        else             { CP_WAIT0(); }
        __syncthreads();

        #pragma unroll 4
        for (int tt = 0; tt < TC; ++tt) {
            float dtc = s_dt[(buf * TC + tt) * CHB + dloc];
            float xcc = s_xc[(buf * TC + tt) * CHB + dloc];
            float4 bq = *reinterpret_cast<const float4*>(&s_bc[(buf * TC + tt) * NSTATE + s0]);
            float u  = dtc * xcc;
            float e0 = __expf(dtc * Av0);
            float e1 = __expf(dtc * Av1);
            h0 = fmaf(e0, h0, u * bq.x);
            h1 = fmaf(e1, h1, u * bq.z);
            float p = fmaf(h1, bq.w, h0 * bq.y);
            p += __shfl_xor_sync(full, p, 4);
            p += __shfl_xor_sync(full, p, 2);
            p += __shfl_xor_sync(full, p, 1);
            if (st) {
                float zc = s_z[(buf * TC + tt) * CHB + dloc];
                float y  = fmaf(xcc, Dv, p);
                float sz = zc / (1.f + __expf(-zc));
                sgh[tt * CHB + dloc] = __float2bfloat16(y * sz);
            }
        }
        __syncthreads();
        {
            int tl0 = tid >> 5;
            int dc  = tid & 31;
            #pragma unroll
            for (int p8 = 0; p8 < 8; ++p8) {
                int tl = p8 * 8 + tl0;
                size_t go = (tokBase + (size_t)c * TC + tl) * DI + d0 + dc;
                gh[go] = sgh[tl * CHB + dc];
            }
        }
        buf ^= 1;
    }
}

// ================= combine =================
__global__ __launch_bounds__(256) void combine_kernel(
    const float* __restrict__ x, const float* __restrict__ alpha,
    const float* __restrict__ yp, float* __restrict__ out)
{
    int idx = blockIdx.x * blockDim.x + threadIdx.x;
    if (idx >= TOK * DM) return;
    int tok = idx / DM;
    int m   = idx - tok * DM;
    float a = 1.f / (1.f + __expf(-alpha[0]));
    int tokb = tok ^ (SEQ - 1);
    float yf = yp[idx];
    float yb = yp[(size_t)TOK * DM + (size_t)tokb * DM + m];
    out[idx] = fmaf(a, yf, fmaf(1.f - a, yb, x[idx]));
}

// ================= launch =================
extern "C" void kernel_launch(void* const* d_in, const int* in_sizes, int n_in,
                              void* d_out, int out_size)
{
    const float* x     = (const float*)d_in[0];
    const float* ln_g  = (const float*)d_in[1];
    const float* ln_b  = (const float*)d_in[2];
    const float* alpha = (const float*)d_in[3];
    const float* f_inw  = (const float*)d_in[4];
    const float* f_cw   = (const float*)d_in[5];
    const float* f_cb   = (const float*)d_in[6];
    const float* f_xw   = (const float*)d_in[7];
    const float* f_dtw  = (const float*)d_in[8];
    const float* f_dtb  = (const float*)d_in[9];
    const float* f_Alog = (const float*)d_in[10];
    const float* f_D    = (const float*)d_in[11];
    const float* f_outw = (const float*)d_in[12];
    const float* b_inw  = (const float*)d_in[13];
    const float* b_cw   = (const float*)d_in[14];
    const float* b_cb   = (const float*)d_in[15];
    const float* b_xw   = (const float*)d_in[16];
    const float* b_dtw  = (const float*)d_in[17];
    const float* b_dtb  = (const float*)d_in[18];
    const float* b_Alog = (const float*)d_in[19];
    const float* b_D    = (const float*)d_in[20];
    const float* b_outw = (const float*)d_in[21];
    float* out = (float*)d_out;

    bf16 *xnh, *winh, *wouth, *gh;
    float *xz, *xc, *dtb_, *yp, *Pp, *Hlp, *Hinp;
    float2 *bc;
    cudaGetSymbolAddress((void**)&xnh,   g_xn_h);
    cudaGetSymbolAddress((void**)&winh,  g_win_h);
    cudaGetSymbolAddress((void**)&wouth, g_wout_h);
    cudaGetSymbolAddress((void**)&gh,    g_gh);
    cudaGetSymbolAddress((void**)&xz,    g_xz);
    cudaGetSymbolAddress((void**)&xc,    g_xc);
    cudaGetSymbolAddress((void**)&bc,    g_bc);
    cudaGetSymbolAddress((void**)&dtb_,  g_dt);
    cudaGetSymbolAddress((void**)&yp,    g_yp);
    cudaGetSymbolAddress((void**)&Pp,    g_P);
    cudaGetSymbolAddress((void**)&Hlp,   g_Hl);
    cudaGetSymbolAddress((void**)&Hinp,  g_Hin);

    const int smemGemm = NSTG * STAGE_B;
    cudaFuncSetAttribute(mma_gemm, cudaFuncAttributeMaxDynamicSharedMemorySize, smemGemm);
    const int smemP1 = 48 * 1024;
    const int smemP2 = 70 * 1024;
    cudaFuncSetAttribute(scan_p1, cudaFuncAttributeMaxDynamicSharedMemorySize, smemP1);
    cudaFuncSetAttribute(scan_p2, cudaFuncAttributeMaxDynamicSharedMemorySize, smemP2);

    // 1) layernorm -> bf16
    ln_kernel<<<TOK, 256>>>(x, ln_g, ln_b, xnh);

    // 2) weight transpose + bf16
    wsplit_kernel<<<dim3(DI2 / 32, DM / 32, 2), dim3(32, 8)>>>(
        f_inw, b_inw, winh, DM, DI2);
    wsplit_kernel<<<dim3(DM / 32, DI / 32, 2), dim3(32, 8)>>>(
        f_outw, b_outw, wouth, DI, DM);

    // 3) in-proj GEMM (1-pass bf16)
    mma_gemm<<<dim3(DI2 / 128, TOK / 128, 2), 512, smemGemm>>>(
        xnh, xnh, winh, winh, xz, TOK, DI2, DM, 0, 1, 1);

    // 4) depthwise conv + SiLU (standalone, fully parallel)
    conv_silu_kernel<<<dim3((TOK * DI) / 256, 1, 2), 256>>>(
        xz, f_cw, b_cw, f_cb, b_cb, xc);

    // 5) bcdt -> packed (B,C) + fused dt softplus
    bcdt_kernel<<<dim3(TOK / 8, 1, 2), 256>>>(
        xc, f_xw, b_xw, f_dtw, b_dtw, f_dtb, b_dtb, bc, dtb_);

    // 6) parallel scan: phase 1, prefix, phase 2 (+gate)
    scan_p1<<<dim3(DI / CHB, 4, NC), 256, smemP1>>>(
        dtb_, xc, bc, f_Alog, b_Alog, Pp, Hlp);
    scan_pre<<<(4 * DI * NSTATE) / 256, 256>>>(Pp, Hlp, Hinp);
    scan_p2<<<dim3(DI / CHB, 4, NC), 256, smemP2>>>(
        dtb_, xc, xz, bc, f_Alog, b_Alog, f_D, b_D, Hinp, gh);

    // 7) out-proj GEMM (1-pass bf16)
    mma_gemm<<<dim3(DM / 128, TOK / 128, 2), 512, smemGemm>>>(
        gh, gh, wouth, wouth, yp, TOK, DM, DI, 1, 0, 1);

    // 8) combine + residual
    combine_kernel<<<(TOK * DM) / 256, 256>>>(x, alpha, yp, out);
}